// round 4
// baseline (speedup 1.0000x reference)
#include <cuda_runtime.h>
#include <cstdint>

#define BB   128      // batch
#define SS   1024     // seq len
#define HH   256      // hidden
#define G4   1024     // 4*H

typedef unsigned long long ull;

// ---------------- scratch (device globals; allocation-free) ----------------
__device__ float g_u[(size_t)SS * BB * G4];   // [s][b][4H]  512 MB

// ---------------- packed fp32x2 helpers (sm_100a) ----------------
__device__ __forceinline__ void fma2(ull &d, ull a, ull b) {
    asm("fma.rn.f32x2 %0, %1, %2, %0;" : "+l"(d) : "l"(a), "l"(b));
}
__device__ __forceinline__ ull pk(float lo, float hi) {
    ull r; asm("mov.b64 %0, {%1, %2};" : "=l"(r) : "f"(lo), "f"(hi)); return r;
}
__device__ __forceinline__ float2 unpk(ull v) {
    float2 r; asm("mov.b64 {%0, %1}, %2;" : "=f"(r.x), "=f"(r.y) : "l"(v)); return r;
}
__device__ __forceinline__ float sigmoid_fast(float x) {
    return __fdividef(1.0f, 1.0f + __expf(-x));
}
__device__ __forceinline__ float tanh_fast(float x) {
    float ax = fabsf(x);
    float e  = __expf(-2.0f * ax);
    float r  = __fdividef(1.0f - e, 1.0f + e);
    return copysignf(r, x);
}
__device__ __forceinline__ unsigned smem_u32(const void* p) {
    unsigned a;
    asm("{ .reg .u64 t; cvta.to.shared.u64 t, %1; cvt.u32.u64 %0, t; }" : "=r"(a) : "l"(p));
    return a;
}

// ============== Kernel 1: u_all = X @ U^T + Ub (f32x2, dup-A) ==============
__global__ __launch_bounds__(256, 2) void u_gemm_kernel(
    const float* __restrict__ X,
    const float* __restrict__ U,
    const float* __restrict__ Ub)
{
    __shared__ float AsD[16][256];   // A duplicated per pair
    __shared__ float Bs[16][132];

    const int s   = blockIdx.y;
    const int bn  = blockIdx.x;
    const int tid = threadIdx.x;
    const int tx  = tid & 15;
    const int ty  = tid >> 4;

    const int lr = tid >> 1;
    const int lk = (tid & 1) * 8;

    const float* Arow = X + ((size_t)lr * SS + s) * HH;
    const float* Brow = U + ((size_t)(bn * 128 + lr)) * HH;

    ull acc2[8][4];
#pragma unroll
    for (int i = 0; i < 8; i++)
#pragma unroll
        for (int j = 0; j < 4; j++) acc2[i][j] = 0ull;

    for (int kk = 0; kk < HH; kk += 16) {
#pragma unroll
        for (int h = 0; h < 2; h++) {
            float4 a = *(const float4*)(Arow + kk + lk + h * 4);
            int kr = lk + h * 4;
            AsD[kr + 0][2 * lr] = a.x;  AsD[kr + 0][2 * lr + 1] = a.x;
            AsD[kr + 1][2 * lr] = a.y;  AsD[kr + 1][2 * lr + 1] = a.y;
            AsD[kr + 2][2 * lr] = a.z;  AsD[kr + 2][2 * lr + 1] = a.z;
            AsD[kr + 3][2 * lr] = a.w;  AsD[kr + 3][2 * lr + 1] = a.w;
            float4 b = *(const float4*)(Brow + kk + lk + h * 4);
            Bs[kr + 0][lr] = b.x;
            Bs[kr + 1][lr] = b.y;
            Bs[kr + 2][lr] = b.z;
            Bs[kr + 3][lr] = b.w;
        }
        __syncthreads();
#pragma unroll
        for (int k = 0; k < 16; k++) {
            const float4* pA = (const float4*)&AsD[k][ty * 16];
            const float4* pB = (const float4*)&Bs[k][tx * 8];
            float4 A0 = pA[0], A1 = pA[1], A2 = pA[2], A3 = pA[3];
            float4 B0 = pB[0], B1 = pB[1];
            ull ad[8] = {pk(A0.x,A0.y), pk(A0.z,A0.w), pk(A1.x,A1.y), pk(A1.z,A1.w),
                         pk(A2.x,A2.y), pk(A2.z,A2.w), pk(A3.x,A3.y), pk(A3.z,A3.w)};
            ull bd[4] = {pk(B0.x,B0.y), pk(B0.z,B0.w), pk(B1.x,B1.y), pk(B1.z,B1.w)};
#pragma unroll
            for (int i = 0; i < 8; i++)
#pragma unroll
                for (int j = 0; j < 4; j++) fma2(acc2[i][j], ad[i], bd[j]);
        }
        __syncthreads();
    }

#pragma unroll
    for (int i = 0; i < 8; i++) {
        const int r = ty * 8 + i;
        float* yrow = g_u + ((size_t)s * BB + r) * G4 + bn * 128;
#pragma unroll
        for (int j2 = 0; j2 < 4; j2++) {
            float2 v = unpk(acc2[i][j2]);
            int c = tx * 8 + 2 * j2;
            yrow[c]     = v.x + Ub[bn * 128 + c];
            yrow[c + 1] = v.y + Ub[bn * 128 + c + 1];
        }
    }
}

// ============== Kernel 2: clustered persistent recurrence ==============
// 16 clusters x 8 CTAs. Cluster cb owns batches [8cb,8cb+8); CTA rank r owns
// j in [32r,32r+32). Thread roles: compute (ks=warp, jl=lane) does partial
// dots over k in [32ks,+32) for all 8 b (weights read ONCE, reused 8x in
// regs); final (b=warp, j=lane) applies gates. 2-phase smem reduction over ks.
// h/c exchanged per step via DSMEM broadcast + cluster barrier.
#define CSZ 8
#define WGATE 33280                       // 32 rows x 65 float4 (1040 B)
#define OFF_W   0                         // 5 gates -> 166400
#define OFF_H   166400                    // [2][8][256] f  -> 16384
#define OFF_C   182784                    // [2][8][256] f  -> 16384
#define OFF_RED 199168                    // [4][5][8][32] f -> 20480
#define SMEM_RECUR 219648

__global__ void __cluster_dims__(CSZ, 1, 1) __launch_bounds__(256, 1)
recur_kernel(const float* __restrict__ ts,      // [B][S]
             const float* __restrict__ Wall,    // [4H][H]
             const float* __restrict__ Wallb,   // [4H]
             const float* __restrict__ Wd,      // [H][H]
             const float* __restrict__ Wdb,     // [H]
             float* __restrict__ out)           // [B][S][H]
{
    extern __shared__ char sm[];
    const int tid  = threadIdx.x;
    const int w    = tid >> 5;           // warp: compute ks / final b-local
    const int lane = tid & 31;           // compute jl / final j-local
    unsigned rank;
    asm("mov.u32 %0, %%cluster_ctarank;" : "=r"(rank));
    const int cb = blockIdx.x / CSZ;
    const int j0 = (int)rank * 32;
    const int b0 = cb * 8;

    // -------- load weight slices once (gate g: f,i,o,c~,d) --------
    {
        const float4* Wall4 = (const float4*)Wall;  // [1024][64]
        const float4* Wd4   = (const float4*)Wd;    // [256][64]
        for (int idx = tid; idx < 5 * 32 * 64; idx += 256) {
            int g   = idx >> 11;
            int rem = idx & 2047;
            int row = rem >> 6;
            int cc  = rem & 63;
            float4 v;
            if (g < 4) v = Wall4[(size_t)(g * 256 + j0 + row) * 64 + cc];
            else       v = Wd4[(size_t)(j0 + row) * 64 + cc];
            *(float4*)(sm + OFF_W + g * WGATE + row * 1040 + cc * 16) = v;
        }
        // zero h/c buffer 0
        for (int idx = tid; idx < 512; idx += 256) {
            *(float4*)(sm + OFF_H + idx * 16) = make_float4(0.f, 0.f, 0.f, 0.f);
            *(float4*)(sm + OFF_C + idx * 16) = make_float4(0.f, 0.f, 0.f, 0.f);
        }
    }

    // biases for final role (j = j0 + lane)
    const int jg = j0 + lane;
    const float bf = Wallb[jg];
    const float bi = Wallb[256 + jg];
    const float bo = Wallb[512 + jg];
    const float bc = Wallb[768 + jg];
    const float bd = Wdb[jg];

    // peer SMEM bases
    unsigned my_base = smem_u32(sm);
    unsigned peer[CSZ];
#pragma unroll
    for (int r2 = 0; r2 < CSZ; r2++)
        asm("mapa.shared::cluster.u32 %0, %1, %2;" : "=r"(peer[r2]) : "r"(my_base), "r"(r2));

    __syncthreads();   // weights + zeroed state visible CTA-wide

    // prefetch step-0 inputs for final role (b = b0 + w)
    const int bfin = b0 + w;
    {
    }
    const float* up0 = g_u + (size_t)bfin * G4 + jg;
    float u0 = up0[0], u1 = up0[256], u2 = up0[512], u3 = up0[768];
    float t  = ts[(size_t)bfin * SS];
    float cprev = 0.0f;                  // this thread owns c[bfin][jg]

    float* redp = (float*)(sm + OFF_RED);
    const unsigned wrow = (unsigned)(lane * 1040 + w * 128);  // jl row + ks k-offset
    const unsigned hcoff_k = (unsigned)(w * 128);             // ks*32 floats

    int cur = 0;
    for (int s = 0; s < SS; s++) {
        ull aF[8], aI[8], aO[8], aC[8], aD[8];
#pragma unroll
        for (int b = 0; b < 8; b++) { aF[b]=0; aI[b]=0; aO[b]=0; aC[b]=0; aD[b]=0; }

        const char* hbase = sm + OFF_H + cur * 8192;
        const char* cbase = sm + OFF_C + cur * 8192;

#pragma unroll
        for (int i = 0; i < 8; i++) {
            const unsigned wo = wrow + i * 16;
            float4 wf = *(const float4*)(sm + OFF_W + 0 * WGATE + wo);
            float4 wi = *(const float4*)(sm + OFF_W + 1 * WGATE + wo);
            float4 wq = *(const float4*)(sm + OFF_W + 2 * WGATE + wo);
            float4 wc = *(const float4*)(sm + OFF_W + 3 * WGATE + wo);
            float4 wd = *(const float4*)(sm + OFF_W + 4 * WGATE + wo);
            ull wf01 = pk(wf.x, wf.y), wf23 = pk(wf.z, wf.w);
            ull wi01 = pk(wi.x, wi.y), wi23 = pk(wi.z, wi.w);
            ull wq01 = pk(wq.x, wq.y), wq23 = pk(wq.z, wq.w);
            ull wc01 = pk(wc.x, wc.y), wc23 = pk(wc.z, wc.w);
            ull wd01 = pk(wd.x, wd.y), wd23 = pk(wd.z, wd.w);
#pragma unroll
            for (int b = 0; b < 8; b++) {
                float4 hv = *(const float4*)(hbase + b * 1024 + hcoff_k + i * 16);
                float4 cv = *(const float4*)(cbase + b * 1024 + hcoff_k + i * 16);
                ull h01 = pk(hv.x, hv.y), h23 = pk(hv.z, hv.w);
                ull c01 = pk(cv.x, cv.y), c23 = pk(cv.z, cv.w);
                fma2(aF[b], h01, wf01); fma2(aF[b], h23, wf23);
                fma2(aI[b], h01, wi01); fma2(aI[b], h23, wi23);
                fma2(aO[b], h01, wq01); fma2(aO[b], h23, wq23);
                fma2(aC[b], h01, wc01); fma2(aC[b], h23, wc23);
                fma2(aD[b], c01, wd01); fma2(aD[b], c23, wd23);
            }
        }

        // finalize partials to scalars
        float pF[8], pI[8], pO[8], pC[8], pD[8];
#pragma unroll
        for (int b = 0; b < 8; b++) {
            float2 v;
            v = unpk(aF[b]); pF[b] = v.x + v.y;
            v = unpk(aI[b]); pI[b] = v.x + v.y;
            v = unpk(aO[b]); pO[b] = v.x + v.y;
            v = unpk(aC[b]); pC[b] = v.x + v.y;
            v = unpk(aD[b]); pD[b] = v.x + v.y;
        }

        // -------- 2-phase reduction over ks --------
        // red[ks2][g][b][jl], ks2 in 0..3
        if (w >= 4) {
            int base = ((w - 4) * 5) * 8 * 32;
#pragma unroll
            for (int b = 0; b < 8; b++) {
                redp[base + (0*8 + b)*32 + lane] = pF[b];
                redp[base + (1*8 + b)*32 + lane] = pI[b];
                redp[base + (2*8 + b)*32 + lane] = pO[b];
                redp[base + (3*8 + b)*32 + lane] = pC[b];
                redp[base + (4*8 + b)*32 + lane] = pD[b];
            }
        }
        __syncthreads();
        if (w < 4) {
            int base = (w * 5) * 8 * 32;
#pragma unroll
            for (int b = 0; b < 8; b++) {
                pF[b] += redp[base + (0*8 + b)*32 + lane];
                pI[b] += redp[base + (1*8 + b)*32 + lane];
                pO[b] += redp[base + (2*8 + b)*32 + lane];
                pC[b] += redp[base + (3*8 + b)*32 + lane];
                pD[b] += redp[base + (4*8 + b)*32 + lane];
            }
#pragma unroll
            for (int b = 0; b < 8; b++) {
                redp[base + (0*8 + b)*32 + lane] = pF[b];
                redp[base + (1*8 + b)*32 + lane] = pI[b];
                redp[base + (2*8 + b)*32 + lane] = pO[b];
                redp[base + (3*8 + b)*32 + lane] = pC[b];
                redp[base + (4*8 + b)*32 + lane] = pD[b];
            }
        }
        __syncthreads();

        // -------- final: thread (b = b0+w, j = j0+lane) --------
        float gF = 0.f, gI = 0.f, gO = 0.f, gC = 0.f, gD = 0.f;
#pragma unroll
        for (int k2 = 0; k2 < 4; k2++) {
            int base = (k2 * 5) * 8 * 32;
            gF += redp[base + (0*8 + w)*32 + lane];
            gI += redp[base + (1*8 + w)*32 + lane];
            gO += redp[base + (2*8 + w)*32 + lane];
            gC += redp[base + (3*8 + w)*32 + lane];
            gD += redp[base + (4*8 + w)*32 + lane];
        }

        float d    = tanh_fast(gD + bd);
        float cadj = cprev - d + d * t;
        float f_   = sigmoid_fast(gF + bf + u0);
        float i_   = sigmoid_fast(gI + bi + u1);
        float o_   = sigmoid_fast(gO + bo + u2);
        float ct   = sigmoid_fast(gC + bc + u3);
        float cn   = f_ * cadj + i_ * ct;
        float hn   = o_ * tanh_fast(cn);
        cprev = cn;

        // -------- broadcast h,c to all 8 CTAs' next buffers --------
        const int nxt = cur ^ 1;
        unsigned hoff = (unsigned)(OFF_H + nxt * 8192 + w * 1024 + jg * 4);
        unsigned coff = (unsigned)(OFF_C + nxt * 8192 + w * 1024 + jg * 4);
#pragma unroll
        for (int r2 = 0; r2 < CSZ; r2++) {
            asm volatile("st.shared::cluster.f32 [%0], %1;" :: "r"(peer[r2] + hoff), "f"(hn) : "memory");
            asm volatile("st.shared::cluster.f32 [%0], %1;" :: "r"(peer[r2] + coff), "f"(cn) : "memory");
        }
        asm volatile("barrier.cluster.arrive.aligned;" ::: "memory");

        // overlap barrier: output store + next-step input prefetch
        out[((size_t)bfin * SS + s) * HH + jg] = hn;
        int sn = (s < SS - 1) ? s + 1 : s;
        const float* upn = g_u + ((size_t)sn * BB + bfin) * G4 + jg;
        u0 = upn[0]; u1 = upn[256]; u2 = upn[512]; u3 = upn[768];
        t  = ts[(size_t)bfin * SS + sn];

        asm volatile("barrier.cluster.wait.aligned;" ::: "memory");
        cur = nxt;
    }
}

// ---------------- launch ----------------
extern "C" void kernel_launch(void* const* d_in, const int* in_sizes, int n_in,
                              void* d_out, int out_size) {
    const float* X     = (const float*)d_in[0];
    const float* tstmp = (const float*)d_in[1];
    const float* Wall  = (const float*)d_in[2];
    const float* Wallb = (const float*)d_in[3];
    const float* U     = (const float*)d_in[4];
    const float* Ub    = (const float*)d_in[5];
    const float* Wdw   = (const float*)d_in[6];
    const float* Wdb   = (const float*)d_in[7];
    float* out = (float*)d_out;

    dim3 ggrid(8, SS);
    u_gemm_kernel<<<ggrid, 256>>>(X, U, Ub);

    cudaFuncSetAttribute(recur_kernel,
                         cudaFuncAttributeMaxDynamicSharedMemorySize, SMEM_RECUR);
    recur_kernel<<<128, 256, SMEM_RECUR>>>(tstmp, Wall, Wallb, Wdw, Wdb, out);
}

// round 5
// speedup vs baseline: 1.0024x; 1.0024x over previous
#include <cuda_runtime.h>
#include <cstdint>

#define BB   128      // batch
#define SS   1024     // seq len
#define HH   256      // hidden
#define G4   1024     // 4*H

typedef unsigned long long ull;

// ---------------- scratch (device globals; allocation-free) ----------------
__device__ float g_u[(size_t)SS * BB * G4];   // [s][b][4H]  512 MB

// ---------------- packed fp32x2 helpers (sm_100a) ----------------
__device__ __forceinline__ void fma2(ull &d, ull a, ull b) {
    asm("fma.rn.f32x2 %0, %1, %2, %0;" : "+l"(d) : "l"(a), "l"(b));
}
__device__ __forceinline__ ull pk(float lo, float hi) {
    ull r; asm("mov.b64 %0, {%1, %2};" : "=l"(r) : "f"(lo), "f"(hi)); return r;
}
__device__ __forceinline__ float2 unpk(ull v) {
    float2 r; asm("mov.b64 {%0, %1}, %2;" : "=f"(r.x), "=f"(r.y) : "l"(v)); return r;
}
__device__ __forceinline__ float sigmoid_fast(float x) {
    return __fdividef(1.0f, 1.0f + __expf(-x));
}
__device__ __forceinline__ float tanh_fast(float x) {
    float ax = fabsf(x);
    float e  = __expf(-2.0f * ax);
    float r  = __fdividef(1.0f - e, 1.0f + e);
    return copysignf(r, x);
}
__device__ __forceinline__ unsigned smem_u32(const void* p) {
    unsigned a;
    asm("{ .reg .u64 t; cvta.to.shared.u64 t, %1; cvt.u32.u64 %0, t; }" : "=r"(a) : "l"(p));
    return a;
}

// ============== Kernel 1: u_all = X @ U^T + Ub (f32x2, dup-A) ==============
__global__ __launch_bounds__(256, 2) void u_gemm_kernel(
    const float* __restrict__ X,
    const float* __restrict__ U,
    const float* __restrict__ Ub)
{
    __shared__ float AsD[16][256];   // A duplicated per pair
    __shared__ float Bs[16][132];

    const int s   = blockIdx.y;
    const int bn  = blockIdx.x;
    const int tid = threadIdx.x;
    const int tx  = tid & 15;
    const int ty  = tid >> 4;

    const int lr = tid >> 1;
    const int lk = (tid & 1) * 8;

    const float* Arow = X + ((size_t)lr * SS + s) * HH;
    const float* Brow = U + ((size_t)(bn * 128 + lr)) * HH;

    ull acc2[8][4];
#pragma unroll
    for (int i = 0; i < 8; i++)
#pragma unroll
        for (int j = 0; j < 4; j++) acc2[i][j] = 0ull;

    for (int kk = 0; kk < HH; kk += 16) {
#pragma unroll
        for (int h = 0; h < 2; h++) {
            float4 a = *(const float4*)(Arow + kk + lk + h * 4);
            int kr = lk + h * 4;
            AsD[kr + 0][2 * lr] = a.x;  AsD[kr + 0][2 * lr + 1] = a.x;
            AsD[kr + 1][2 * lr] = a.y;  AsD[kr + 1][2 * lr + 1] = a.y;
            AsD[kr + 2][2 * lr] = a.z;  AsD[kr + 2][2 * lr + 1] = a.z;
            AsD[kr + 3][2 * lr] = a.w;  AsD[kr + 3][2 * lr + 1] = a.w;
            float4 b = *(const float4*)(Brow + kk + lk + h * 4);
            Bs[kr + 0][lr] = b.x;
            Bs[kr + 1][lr] = b.y;
            Bs[kr + 2][lr] = b.z;
            Bs[kr + 3][lr] = b.w;
        }
        __syncthreads();
#pragma unroll
        for (int k = 0; k < 16; k++) {
            const float4* pA = (const float4*)&AsD[k][ty * 16];
            const float4* pB = (const float4*)&Bs[k][tx * 8];
            float4 A0 = pA[0], A1 = pA[1], A2 = pA[2], A3 = pA[3];
            float4 B0 = pB[0], B1 = pB[1];
            ull ad[8] = {pk(A0.x,A0.y), pk(A0.z,A0.w), pk(A1.x,A1.y), pk(A1.z,A1.w),
                         pk(A2.x,A2.y), pk(A2.z,A2.w), pk(A3.x,A3.y), pk(A3.z,A3.w)};
            ull bd[4] = {pk(B0.x,B0.y), pk(B0.z,B0.w), pk(B1.x,B1.y), pk(B1.z,B1.w)};
#pragma unroll
            for (int i = 0; i < 8; i++)
#pragma unroll
                for (int j = 0; j < 4; j++) fma2(acc2[i][j], ad[i], bd[j]);
        }
        __syncthreads();
    }

#pragma unroll
    for (int i = 0; i < 8; i++) {
        const int r = ty * 8 + i;
        float* yrow = g_u + ((size_t)s * BB + r) * G4 + bn * 128;
#pragma unroll
        for (int j2 = 0; j2 < 4; j2++) {
            float2 v = unpk(acc2[i][j2]);
            int c = tx * 8 + 2 * j2;
            yrow[c]     = v.x + Ub[bn * 128 + c];
            yrow[c + 1] = v.y + Ub[bn * 128 + c + 1];
        }
    }
}

// ============== Kernel 2: clustered persistent recurrence ==============
// 16 clusters x 8 CTAs. Cluster cb owns batches [8cb,8cb+8); CTA rank r owns
// j in [32r,32r+32). Thread roles: compute (ks=warp, jl=lane) does partial
// dots over k in [32ks,+32) for all 8 b (weights read ONCE, reused 8x in
// regs); final (b=warp, j=lane) applies gates. 2-phase smem reduction over ks.
// h/c exchanged per step via DSMEM broadcast + cluster barrier.
#define CSZ 8
#define WGATE 33280                       // 32 rows x 65 float4 (1040 B)
#define OFF_W   0                         // 5 gates -> 166400
#define OFF_H   166400                    // [2][8][256] f  -> 16384
#define OFF_C   182784                    // [2][8][256] f  -> 16384
#define OFF_RED 199168                    // [4][5][8][32] f -> 20480
#define SMEM_RECUR 219648

__global__ void __cluster_dims__(CSZ, 1, 1) __launch_bounds__(256, 1)
recur_kernel(const float* __restrict__ ts,      // [B][S]
             const float* __restrict__ Wall,    // [4H][H]
             const float* __restrict__ Wallb,   // [4H]
             const float* __restrict__ Wd,      // [H][H]
             const float* __restrict__ Wdb,     // [H]
             float* __restrict__ out)           // [B][S][H]
{
    extern __shared__ char sm[];
    const int tid  = threadIdx.x;
    const int w    = tid >> 5;           // warp: compute ks / final b-local
    const int lane = tid & 31;           // compute jl / final j-local
    unsigned rank;
    asm("mov.u32 %0, %%cluster_ctarank;" : "=r"(rank));
    const int cb = blockIdx.x / CSZ;
    const int j0 = (int)rank * 32;
    const int b0 = cb * 8;

    // -------- load weight slices once (gate g: f,i,o,c~,d) --------
    {
        const float4* Wall4 = (const float4*)Wall;  // [1024][64]
        const float4* Wd4   = (const float4*)Wd;    // [256][64]
        for (int idx = tid; idx < 5 * 32 * 64; idx += 256) {
            int g   = idx >> 11;
            int rem = idx & 2047;
            int row = rem >> 6;
            int cc  = rem & 63;
            float4 v;
            if (g < 4) v = Wall4[(size_t)(g * 256 + j0 + row) * 64 + cc];
            else       v = Wd4[(size_t)(j0 + row) * 64 + cc];
            *(float4*)(sm + OFF_W + g * WGATE + row * 1040 + cc * 16) = v;
        }
        // zero h/c buffer 0
        for (int idx = tid; idx < 512; idx += 256) {
            *(float4*)(sm + OFF_H + idx * 16) = make_float4(0.f, 0.f, 0.f, 0.f);
            *(float4*)(sm + OFF_C + idx * 16) = make_float4(0.f, 0.f, 0.f, 0.f);
        }
    }

    // biases for final role (j = j0 + lane)
    const int jg = j0 + lane;
    const float bf = Wallb[jg];
    const float bi = Wallb[256 + jg];
    const float bo = Wallb[512 + jg];
    const float bc = Wallb[768 + jg];
    const float bd = Wdb[jg];

    // peer SMEM bases
    unsigned my_base = smem_u32(sm);
    unsigned peer[CSZ];
#pragma unroll
    for (int r2 = 0; r2 < CSZ; r2++)
        asm("mapa.shared::cluster.u32 %0, %1, %2;" : "=r"(peer[r2]) : "r"(my_base), "r"(r2));

    __syncthreads();   // weights + zeroed state visible CTA-wide

    // prefetch step-0 inputs for final role (b = b0 + w)
    const int bfin = b0 + w;
    {
    }
    const float* up0 = g_u + (size_t)bfin * G4 + jg;
    float u0 = up0[0], u1 = up0[256], u2 = up0[512], u3 = up0[768];
    float t  = ts[(size_t)bfin * SS];
    float cprev = 0.0f;                  // this thread owns c[bfin][jg]

    float* redp = (float*)(sm + OFF_RED);
    const unsigned wrow = (unsigned)(lane * 1040 + w * 128);  // jl row + ks k-offset
    const unsigned hcoff_k = (unsigned)(w * 128);             // ks*32 floats

    int cur = 0;
    for (int s = 0; s < SS; s++) {
        ull aF[8], aI[8], aO[8], aC[8], aD[8];
#pragma unroll
        for (int b = 0; b < 8; b++) { aF[b]=0; aI[b]=0; aO[b]=0; aC[b]=0; aD[b]=0; }

        const char* hbase = sm + OFF_H + cur * 8192;
        const char* cbase = sm + OFF_C + cur * 8192;

#pragma unroll
        for (int i = 0; i < 8; i++) {
            const unsigned wo = wrow + i * 16;
            float4 wf = *(const float4*)(sm + OFF_W + 0 * WGATE + wo);
            float4 wi = *(const float4*)(sm + OFF_W + 1 * WGATE + wo);
            float4 wq = *(const float4*)(sm + OFF_W + 2 * WGATE + wo);
            float4 wc = *(const float4*)(sm + OFF_W + 3 * WGATE + wo);
            float4 wd = *(const float4*)(sm + OFF_W + 4 * WGATE + wo);
            ull wf01 = pk(wf.x, wf.y), wf23 = pk(wf.z, wf.w);
            ull wi01 = pk(wi.x, wi.y), wi23 = pk(wi.z, wi.w);
            ull wq01 = pk(wq.x, wq.y), wq23 = pk(wq.z, wq.w);
            ull wc01 = pk(wc.x, wc.y), wc23 = pk(wc.z, wc.w);
            ull wd01 = pk(wd.x, wd.y), wd23 = pk(wd.z, wd.w);
#pragma unroll
            for (int b = 0; b < 8; b++) {
                float4 hv = *(const float4*)(hbase + b * 1024 + hcoff_k + i * 16);
                float4 cv = *(const float4*)(cbase + b * 1024 + hcoff_k + i * 16);
                ull h01 = pk(hv.x, hv.y), h23 = pk(hv.z, hv.w);
                ull c01 = pk(cv.x, cv.y), c23 = pk(cv.z, cv.w);
                fma2(aF[b], h01, wf01); fma2(aF[b], h23, wf23);
                fma2(aI[b], h01, wi01); fma2(aI[b], h23, wi23);
                fma2(aO[b], h01, wq01); fma2(aO[b], h23, wq23);
                fma2(aC[b], h01, wc01); fma2(aC[b], h23, wc23);
                fma2(aD[b], c01, wd01); fma2(aD[b], c23, wd23);
            }
        }

        // finalize partials to scalars
        float pF[8], pI[8], pO[8], pC[8], pD[8];
#pragma unroll
        for (int b = 0; b < 8; b++) {
            float2 v;
            v = unpk(aF[b]); pF[b] = v.x + v.y;
            v = unpk(aI[b]); pI[b] = v.x + v.y;
            v = unpk(aO[b]); pO[b] = v.x + v.y;
            v = unpk(aC[b]); pC[b] = v.x + v.y;
            v = unpk(aD[b]); pD[b] = v.x + v.y;
        }

        // -------- 2-phase reduction over ks --------
        // red[ks2][g][b][jl], ks2 in 0..3
        if (w >= 4) {
            int base = ((w - 4) * 5) * 8 * 32;
#pragma unroll
            for (int b = 0; b < 8; b++) {
                redp[base + (0*8 + b)*32 + lane] = pF[b];
                redp[base + (1*8 + b)*32 + lane] = pI[b];
                redp[base + (2*8 + b)*32 + lane] = pO[b];
                redp[base + (3*8 + b)*32 + lane] = pC[b];
                redp[base + (4*8 + b)*32 + lane] = pD[b];
            }
        }
        __syncthreads();
        if (w < 4) {
            int base = (w * 5) * 8 * 32;
#pragma unroll
            for (int b = 0; b < 8; b++) {
                pF[b] += redp[base + (0*8 + b)*32 + lane];
                pI[b] += redp[base + (1*8 + b)*32 + lane];
                pO[b] += redp[base + (2*8 + b)*32 + lane];
                pC[b] += redp[base + (3*8 + b)*32 + lane];
                pD[b] += redp[base + (4*8 + b)*32 + lane];
            }
#pragma unroll
            for (int b = 0; b < 8; b++) {
                redp[base + (0*8 + b)*32 + lane] = pF[b];
                redp[base + (1*8 + b)*32 + lane] = pI[b];
                redp[base + (2*8 + b)*32 + lane] = pO[b];
                redp[base + (3*8 + b)*32 + lane] = pC[b];
                redp[base + (4*8 + b)*32 + lane] = pD[b];
            }
        }
        __syncthreads();

        // -------- final: thread (b = b0+w, j = j0+lane) --------
        float gF = 0.f, gI = 0.f, gO = 0.f, gC = 0.f, gD = 0.f;
#pragma unroll
        for (int k2 = 0; k2 < 4; k2++) {
            int base = (k2 * 5) * 8 * 32;
            gF += redp[base + (0*8 + w)*32 + lane];
            gI += redp[base + (1*8 + w)*32 + lane];
            gO += redp[base + (2*8 + w)*32 + lane];
            gC += redp[base + (3*8 + w)*32 + lane];
            gD += redp[base + (4*8 + w)*32 + lane];
        }

        float d    = tanh_fast(gD + bd);
        float cadj = cprev - d + d * t;
        float f_   = sigmoid_fast(gF + bf + u0);
        float i_   = sigmoid_fast(gI + bi + u1);
        float o_   = sigmoid_fast(gO + bo + u2);
        float ct   = sigmoid_fast(gC + bc + u3);
        float cn   = f_ * cadj + i_ * ct;
        float hn   = o_ * tanh_fast(cn);
        cprev = cn;

        // -------- broadcast h,c to all 8 CTAs' next buffers --------
        const int nxt = cur ^ 1;
        unsigned hoff = (unsigned)(OFF_H + nxt * 8192 + w * 1024 + jg * 4);
        unsigned coff = (unsigned)(OFF_C + nxt * 8192 + w * 1024 + jg * 4);
#pragma unroll
        for (int r2 = 0; r2 < CSZ; r2++) {
            asm volatile("st.shared::cluster.f32 [%0], %1;" :: "r"(peer[r2] + hoff), "f"(hn) : "memory");
            asm volatile("st.shared::cluster.f32 [%0], %1;" :: "r"(peer[r2] + coff), "f"(cn) : "memory");
        }
        asm volatile("barrier.cluster.arrive.aligned;" ::: "memory");

        // overlap barrier: output store + next-step input prefetch
        out[((size_t)bfin * SS + s) * HH + jg] = hn;
        int sn = (s < SS - 1) ? s + 1 : s;
        const float* upn = g_u + ((size_t)sn * BB + bfin) * G4 + jg;
        u0 = upn[0]; u1 = upn[256]; u2 = upn[512]; u3 = upn[768];
        t  = ts[(size_t)bfin * SS + sn];

        asm volatile("barrier.cluster.wait.aligned;" ::: "memory");
        cur = nxt;
    }
}

// ---------------- launch ----------------
extern "C" void kernel_launch(void* const* d_in, const int* in_sizes, int n_in,
                              void* d_out, int out_size) {
    const float* X     = (const float*)d_in[0];
    const float* tstmp = (const float*)d_in[1];
    const float* Wall  = (const float*)d_in[2];
    const float* Wallb = (const float*)d_in[3];
    const float* U     = (const float*)d_in[4];
    const float* Ub    = (const float*)d_in[5];
    const float* Wdw   = (const float*)d_in[6];
    const float* Wdb   = (const float*)d_in[7];
    float* out = (float*)d_out;

    dim3 ggrid(8, SS);
    u_gemm_kernel<<<ggrid, 256>>>(X, U, Ub);

    cudaFuncSetAttribute(recur_kernel,
                         cudaFuncAttributeMaxDynamicSharedMemorySize, SMEM_RECUR);
    recur_kernel<<<128, 256, SMEM_RECUR>>>(tstmp, Wall, Wallb, Wdw, Wdb, out);
}